// round 1
// baseline (speedup 1.0000x reference)
#include <cuda_runtime.h>
#include <math.h>

#define Bsz 16
#define Tn 16
#define FDIM 64
#define ODIM 8
#define NQ 10
#define NA 4
#define NROTS 80
#define QROTS 40
#define NS 1024            // 2^NQ
#define NANC 16            // 2^NA
#define STATE_PER_B (NS*NANC)   // 16384
#define TOTAL_AMPS (Bsz*STATE_PER_B)

// layout: state[ ((b*16 + a) << 10) | s ]  -> each (b,a) block contiguous 1024 complex
__device__ float2 g_state[TOTAL_AMPS];
__device__ float2 g_csn[Bsz*Tn*NROTS];   // per (b,t) cos/sin of theta/2
__device__ float2 g_qff[QROTS];
__device__ float2 g_M[3][256];           // M1, M2, F  (16x16 each, row-major)
__device__ float2 g_v0[16];

// ---------------------------------------------------------------- angles ----
__global__ void k_angles(const float* __restrict__ x,
                         const float* __restrict__ Wfp,
                         const float* __restrict__ bfp)
{
    int bt = blockIdx.x;           // b*16 + t
    int b = bt >> 4, t = bt & 15;
    __shared__ float h[64];
    int tid = threadIdx.x;
    if (tid < 64) {
        int f = tid;
        int k = f >> 1;
        float div = expf((float)(2*k) * (-logf(10000.0f) / 64.0f));
        float arg = (float)t * div;
        float pe = (f & 1) ? cosf(arg) : sinf(arg);
        h[f] = x[(b*64 + f)*16 + t] + pe;
    }
    __syncthreads();
    if (tid < NROTS) {
        float acc = bfp[tid];
        const float* w = Wfp + tid*64;
        #pragma unroll
        for (int f = 0; f < 64; ++f) acc += h[f]*w[f];
        float sg = 1.0f / (1.0f + expf(-acc));
        // theta = 2*pi*sg ; need cos/sin of theta/2 = pi*sg
        float sn, cs;
        sincosf(3.14159265358979323846f * sg, &sn, &cs);
        g_csn[bt*NROTS + tid] = make_float2(cs, sn);
    }
}

// -------------------------------------------------------------- setup -------
// builds U_prep (16x16), then M1=U D1 U^H, M2=U D2 U^H, F=D3 U^H, v0=e^{i phi0} U[:,0]
__global__ void k_setup(const float* __restrict__ prep_p,
                        const float* __restrict__ sig_ang,
                        const float* __restrict__ qff_p)
{
    __shared__ float2 sU[16][16];   // [row][col]
    int t = threadIdx.x;
    if (t < 16) {
        float2 v[16];
        #pragma unroll
        for (int i = 0; i < 16; ++i) v[i] = make_float2(0.f, 0.f);
        v[t] = make_float2(1.f, 0.f);
        for (int ly = 0; ly < 4; ++ly) {
            for (int qi = 0; qi < 4; ++qi) {
                int p = 3 - qi;
                float thy = prep_p[(ly*4 + qi)*2 + 0];
                float thz = prep_p[(ly*4 + qi)*2 + 1];
                float c, s;
                sincosf(0.5f*thy, &s, &c);
                for (int m = 0; m < 8; ++m) {
                    int i0 = ((m >> p) << (p+1)) | (m & ((1 << p) - 1));
                    int i1 = i0 | (1 << p);
                    float2 a0 = v[i0], a1 = v[i1];
                    v[i0] = make_float2(c*a0.x - s*a1.x, c*a0.y - s*a1.y);
                    v[i1] = make_float2(s*a0.x + c*a1.x, s*a0.y + c*a1.y);
                }
                float cz, sz;
                sincosf(0.5f*thz, &sz, &cz);
                for (int i = 0; i < 16; ++i) {
                    float im = ((i >> p) & 1) ? sz : -sz;   // e^{+-i thz/2}
                    float2 a = v[i];
                    v[i] = make_float2(cz*a.x - im*a.y, cz*a.y + im*a.x);
                }
            }
            for (int i = 0; i < 3; ++i) {
                int pc = 3 - i, pt = 2 - i;
                for (int idx = 0; idx < 16; ++idx) {
                    if (((idx >> pc) & 1) == 1 && ((idx >> pt) & 1) == 0) {
                        int j = idx | (1 << pt);
                        float2 tmp = v[idx]; v[idx] = v[j]; v[j] = tmp;
                    }
                }
            }
        }
        #pragma unroll
        for (int r = 0; r < 16; ++r) sU[r][t] = v[r];
    }
    __syncthreads();
    if (t < 16) {
        // v0 = e^{i phi0} * U[:,0]
        float c0, s0;
        sincosf(sig_ang[0], &s0, &c0);
        float2 u = sU[t][0];
        g_v0[t] = make_float2(c0*u.x - s0*u.y, c0*u.y + s0*u.x);

        // M_m[j][k] = sum_a U[j][a] * d_a * conj(U[k][a]),  thread t = column k
        for (int m = 0; m < 2; ++m) {
            float cp, sp;
            sincosf(sig_ang[m+1], &sp, &cp);
            for (int j = 0; j < 16; ++j) {
                float2 acc = make_float2(0.f, 0.f);
                for (int a = 0; a < 16; ++a) {
                    float2 uja = sU[j][a];
                    float2 uka = sU[t][a];
                    float dr = cp, di = (a == 0) ? sp : -sp;
                    // d * conj(uka)
                    float2 dc = make_float2(dr*uka.x + di*uka.y, di*uka.x - dr*uka.y);
                    acc.x += uja.x*dc.x - uja.y*dc.y;
                    acc.y += uja.x*dc.y + uja.y*dc.x;
                }
                g_M[m][j*16 + t] = acc;
            }
        }
        // F[j][k] = d_j(phi3) * conj(U[k][j])
        float cp, sp;
        sincosf(sig_ang[3], &sp, &cp);
        for (int j = 0; j < 16; ++j) {
            float dr = cp, di = (j == 0) ? sp : -sp;
            float2 u2 = sU[t][j];
            g_M[2][j*16 + t] = make_float2(dr*u2.x + di*u2.y, di*u2.x - dr*u2.y);
        }
    }
    if (t < QROTS) {
        float c, s;
        sincosf(0.5f * qff_p[t], &s, &c);
        g_qff[t] = make_float2(c, s);
    }
}

// -------------------------------------------------------------- init --------
__global__ void k_init()
{
    int idx = blockIdx.x * blockDim.x + threadIdx.x;
    if (idx < TOTAL_AMPS) {
        float2 v = make_float2(0.f, 0.f);
        if ((idx & 1023) == 0) v = g_v0[(idx >> 10) & 15];
        g_state[idx] = v;
    }
}

// ------------------------------------------------------------- select -------
// One CTA per (b,a) pair. Applies sim14 (ngates gates) to its contiguous
// 1024-amp block in shared memory.
__global__ void __launch_bounds__(256) k_select(int ngates, int adjoint, int useQff)
{
    int c = blockIdx.x;                 // b*16 + a (= b*16 + t)
    const float2* ang = useQff ? g_qff : (g_csn + c*NROTS);
    __shared__ float2 sv[NS];
    float2* gb = g_state + ((size_t)c << 10);
    for (int i = threadIdx.x; i < NS; i += 256) sv[i] = gb[i];
    __syncthreads();

    for (int g = 0; g < ngates; ++g) {
        int ga = adjoint ? (ngates - 1 - g) : g;
        int l = ga / 40, r = ga - 40*l;
        float2 cs = ang[ga];
        float cc = cs.x;
        float ss = adjoint ? -cs.y : cs.y;

        if (r < 10 || (r >= 20 && r < 30)) {
            // RY on qubit q  (bit p = 9-q)
            int q = (r < 10) ? r : (r - 20);
            int p = 9 - q;
            #pragma unroll 2
            for (int k = threadIdx.x; k < 512; k += 256) {
                int i0 = ((k >> p) << (p+1)) | (k & ((1 << p) - 1));
                int i1 = i0 | (1 << p);
                float2 a0 = sv[i0], a1 = sv[i1];
                sv[i0] = make_float2(cc*a0.x - ss*a1.x, cc*a0.y - ss*a1.y);
                sv[i1] = make_float2(ss*a0.x + cc*a1.x, ss*a0.y + cc*a1.y);
            }
        } else {
            // CRX(control ci, target tg)
            int ci, tg;
            if (r < 20) { int j = r - 10; ci = 9 - j; tg = (ci + 1) % 10; }
            else        { int j = r - 30; ci = (j == 0) ? 9 : (j - 1); tg = (ci + 9) % 10; }
            int pc = 9 - ci, pt = 9 - tg;
            int p1 = pc < pt ? pc : pt;
            int p2 = pc < pt ? pt : pc;
            int k = threadIdx.x;
            if (k < 256) {
                int xv = ((k >> p1) << (p1+1)) | (k & ((1 << p1) - 1));
                xv = ((xv >> p2) << (p2+1)) | (xv & ((1 << p2) - 1));
                int i0 = xv | (1 << pc);
                int i1 = i0 | (1 << pt);
                float2 a0 = sv[i0], a1 = sv[i1];
                // block [[c, -i s],[-i s, c]]
                sv[i0] = make_float2(cc*a0.x + ss*a1.y, cc*a0.y - ss*a1.x);
                sv[i1] = make_float2(ss*a0.y + cc*a1.x, -ss*a0.x + cc*a1.y);
            }
        }
        __syncthreads();
    }
    for (int i = threadIdx.x; i < NS; i += 256) gb[i] = sv[i];
}

// ---------------------------------------------------------- ancilla mat -----
// Applies 16x16 matrix g_M[mi] over the ancilla index for every (b,s).
__global__ void __launch_bounds__(256) k_anc(int mi)
{
    int bk = blockIdx.x;               // 16 batches * 64 s-groups
    int b = bk >> 6, s0 = (bk & 63) << 4;
    __shared__ float2 vin[16][17];     // [a][sl] padded
    __shared__ float2 sM[256];
    int tid = threadIdx.x;
    int a = tid >> 4, sl = tid & 15;
    sM[tid] = g_M[mi][tid];
    size_t idx = (((size_t)(b << 4) | a) << 10) + s0 + sl;
    vin[a][sl] = g_state[idx];
    __syncthreads();
    float2 acc = make_float2(0.f, 0.f);
    #pragma unroll
    for (int k2 = 0; k2 < 16; ++k2) {
        float2 m = sM[a*16 + k2];
        float2 v = vin[k2][sl];
        acc.x += m.x*v.x - m.y*v.y;
        acc.y += m.x*v.y + m.y*v.x;
    }
    g_state[idx] = acc;
}

// ------------------------------------------------------------ expvals -------
__global__ void __launch_bounds__(256) k_expvals(const float* __restrict__ W_out,
                                                 const float* __restrict__ b_out,
                                                 float* __restrict__ out)
{
    int b = blockIdx.x;
    const float2* st = g_state + ((size_t)b << 14);
    __shared__ float ex[30];
    __shared__ float red[8][3];
    int tid = threadIdx.x;

    for (int i = 0; i < NQ; ++i) {
        int p = 9 - i;
        float cr = 0.f, cim = 0.f, zz = 0.f;
        for (int pk = tid; pk < 8192; pk += 256) {
            int a = pk >> 9, m = pk & 511;
            int s0 = ((m >> p) << (p+1)) | (m & ((1 << p) - 1));
            int f0 = (a << 10) | s0;
            float2 a0 = st[f0];
            float2 a1 = st[f0 | (1 << p)];
            cr  += a0.x*a1.x + a0.y*a1.y;
            cim += a0.x*a1.y - a0.y*a1.x;
            zz  += (a0.x*a0.x + a0.y*a0.y) - (a1.x*a1.x + a1.y*a1.y);
        }
        #pragma unroll
        for (int off = 16; off; off >>= 1) {
            cr  += __shfl_down_sync(0xffffffffu, cr,  off);
            cim += __shfl_down_sync(0xffffffffu, cim, off);
            zz  += __shfl_down_sync(0xffffffffu, zz,  off);
        }
        if ((tid & 31) == 0) {
            int w = tid >> 5;
            red[w][0] = cr; red[w][1] = cim; red[w][2] = zz;
        }
        __syncthreads();
        if (tid == 0) {
            float A = 0.f, Bv = 0.f, C = 0.f;
            #pragma unroll
            for (int w = 0; w < 8; ++w) { A += red[w][0]; Bv += red[w][1]; C += red[w][2]; }
            ex[i]      = 2.f * A;
            ex[10 + i] = 2.f * Bv;
            ex[20 + i] = C;
        }
        __syncthreads();
    }
    if (tid < ODIM) {
        float acc = b_out[tid];
        #pragma unroll
        for (int j = 0; j < 30; ++j) acc += W_out[tid*30 + j] * ex[j];
        out[b*ODIM + tid] = acc;
    }
}

// ------------------------------------------------------------ launch --------
extern "C" void kernel_launch(void* const* d_in, const int* in_sizes, int n_in,
                              void* d_out, int out_size)
{
    const float* x       = (const float*)d_in[0];
    const float* W_fp    = (const float*)d_in[1];
    const float* b_fp    = (const float*)d_in[2];
    const float* prep_p  = (const float*)d_in[3];
    const float* sig_ang = (const float*)d_in[4];
    const float* qff_p   = (const float*)d_in[5];
    const float* W_out   = (const float*)d_in[6];
    const float* b_out   = (const float*)d_in[7];
    float* out = (float*)d_out;

    k_angles<<<Bsz*Tn, 128>>>(x, W_fp, b_fp);
    k_setup<<<1, 64>>>(prep_p, sig_ang, qff_p);
    k_init<<<(TOTAL_AMPS + 511)/512, 512>>>();

    // k = 0
    k_select<<<256, 256>>>(NROTS, 0, 0);
    k_anc<<<1024, 256>>>(0);
    // k = 1 (adjoint select)
    k_select<<<256, 256>>>(NROTS, 1, 0);
    k_anc<<<1024, 256>>>(1);
    // k = 2
    k_select<<<256, 256>>>(NROTS, 0, 0);
    k_anc<<<1024, 256>>>(2);      // F = D(phi3) * U^H

    // qff sim14, layers=1, uniform params
    k_select<<<256, 256>>>(QROTS, 0, 1);

    k_expvals<<<Bsz, 256>>>(W_out, b_out, out);
}